// round 9
// baseline (speedup 1.0000x reference)
#include <cuda_runtime.h>

// LBP (radius=1, 8 points, skimage 'default') over NCHW fp32, zero boundary.
// f32x2-packed bilinear core: rows are stored as five 64-bit pairs
// e01=(b0,b1) e23=(b2,b3) e45=(b4,b5) o12=(b1,b2) o34=(b3,b4), so every
// bilinear operand for both pixel-pairs is a ready-made pair -> 8 packed
// FMA-class ops per pixel instead of 16 scalar FFMA. Compare scalars are the
// pair halves (free). Geometry: 4x8 strip/thread, block (56,4), grid (1,7,P).

typedef unsigned long long u64;

__device__ __forceinline__ u64 pk(float lo, float hi) {
    u64 r; asm("mov.b64 %0, {%1, %2};" : "=l"(r) : "f"(lo), "f"(hi)); return r;
}
__device__ __forceinline__ float2 up(u64 v) {
    float2 r; asm("mov.b64 {%0, %1}, %2;" : "=f"(r.x), "=f"(r.y) : "l"(v)); return r;
}
__device__ __forceinline__ u64 mul2(u64 a, u64 b) {
    u64 d; asm("mul.rn.f32x2 %0, %1, %2;" : "=l"(d) : "l"(a), "l"(b)); return d;
}
__device__ __forceinline__ u64 fma2(u64 a, u64 b, u64 c) {
    u64 d; asm("fma.rn.f32x2 %0, %1, %2, %3;" : "=l"(d) : "l"(a), "l"(b), "l"(c)); return d;
}

struct Row { u64 e01, e23, e45, o12, o34; };

__global__ __launch_bounds__(224) void lbp_kernel(
    const float* __restrict__ in, float* __restrict__ out)
{
    constexpr int H = 224, W = 224;

    const int plane = blockIdx.z;
    const float* ip = in + (size_t)plane * (H * W);
    float*       op = out + (size_t)plane * (H * W);

    const int tx = threadIdx.x;                        // column group 0..55
    const int x0 = tx * 4;
    const int y0 = blockIdx.y * 32 + threadIdx.y * 8;  // strip row base

    const bool has_left  = (tx > 0);
    const bool has_right = (tx < 55);

    // Bilinear weights (float32 of double products, as jax produces).
    const double Fd = 0.70710678;
    const double Gd = 1.0 - Fd;
    const float WD = (float)(Fd * Fd);
    const float WE = (float)(Fd * Gd);
    const float WC = (float)(Gd * Gd);
    const u64 WD2 = pk(WD, WD), WE2 = pk(WE, WE), WC2 = pk(WC, WC);

    // Scalar staging for a freshly loaded row: [left, v0..v3, right]
    auto load_stage = [&](float* s, int k) {
        const int gy = y0 + k;
        if ((unsigned)gy < (unsigned)H) {
            const float* rp = ip + gy * W + x0;
            const float4 v = *reinterpret_cast<const float4*>(rp);
            s[0] = has_left  ? __ldg(rp - 1) : 0.0f;
            s[1] = v.x; s[2] = v.y; s[3] = v.z; s[4] = v.w;
            s[5] = has_right ? __ldg(rp + 4) : 0.0f;
        } else {
            s[0] = s[1] = s[2] = s[3] = s[4] = s[5] = 0.0f;
        }
    };
    auto to_row = [&](Row& r, const float* s) {
        r.e01 = pk(s[0], s[1]);
        r.e23 = pk(s[2], s[3]);
        r.e45 = pk(s[4], s[5]);
        r.o12 = pk(s[1], s[2]);
        r.o34 = pk(s[3], s[4]);
    };

    Row rows[3];
    float stg[6];

    // Prologue: rows -1,0,1 packed; row 2 staged (prefetch).
    load_stage(stg, -1); to_row(rows[0], stg);
    load_stage(stg,  0); to_row(rows[1], stg);
    load_stage(stg,  1); to_row(rows[2], stg);
    load_stage(stg,  2);

    float* wp = op + y0 * W + x0;

    #pragma unroll
    for (int r = 0; r < 8; r++) {
        const Row& N = rows[r % 3];
        const Row& C = rows[(r + 1) % 3];
        const Row& S = rows[(r + 2) % 3];

        float4 res;

        // Packed diagonal samples; chain order matches the bit-stable scalar
        // version: v = ((t1 + t2) + t3) + t4 left-associated.
        #pragma unroll
        for (int gsel = 0; gsel < 2; gsel++) {
            const u64 nw = gsel ? N.e23 : N.e01;
            const u64 nn = gsel ? N.o34 : N.o12;
            const u64 ne = gsel ? N.e45 : N.e23;
            const u64 wwp = gsel ? C.e23 : C.e01;
            const u64 cc  = gsel ? C.o34 : C.o12;
            const u64 eep = gsel ? C.e45 : C.e23;
            const u64 sw = gsel ? S.e23 : S.e01;
            const u64 ssp = gsel ? S.o34 : S.o12;
            const u64 se = gsel ? S.e45 : S.e23;

            // v1 = ((WE*nn + WD*ne) + WC*c) + WE*ee   (up-right)
            const u64 v1 = fma2(WE2, eep, fma2(WC2, cc, fma2(WD2, ne, mul2(WE2, nn))));
            // v3 = ((WD*nw + WE*nn) + WE*ww) + WC*c   (up-left)
            const u64 v3 = fma2(WC2, cc, fma2(WE2, wwp, fma2(WE2, nn, mul2(WD2, nw))));
            // v5 = ((WE*ww + WC*c) + WD*sw) + WE*ss   (down-left)
            const u64 v5 = fma2(WE2, ssp, fma2(WD2, sw, fma2(WC2, cc, mul2(WE2, wwp))));
            // v7 = ((WC*c + WE*ee) + WE*ss) + WD*se   (down-right)
            const u64 v7 = fma2(WD2, se, fma2(WE2, ssp, fma2(WE2, eep, mul2(WC2, cc))));

            const float2 c2  = up(cc);
            const float2 nn2 = up(nn);
            const float2 ss2 = up(ssp);
            const float2 ww2 = up(wwp);
            const float2 ee2 = up(eep);
            const float2 V1 = up(v1), V3 = up(v3), V5 = up(v5), V7 = up(v7);

            // lane 0 of the pair
            {
                const float c = c2.x;
                float code = (ee2.x >= c) ? 1.0f : 0.0f;
                if (V1.x  >= c) code += 2.0f;
                if (nn2.x >= c) code += 4.0f;
                if (V3.x  >= c) code += 8.0f;
                if (ww2.x >= c) code += 16.0f;
                if (V5.x  >= c) code += 32.0f;
                if (ss2.x >= c) code += 64.0f;
                if (V7.x  >= c) code += 128.0f;
                if (gsel) res.z = code; else res.x = code;
            }
            // lane 1 of the pair
            {
                const float c = c2.y;
                float code = (ee2.y >= c) ? 1.0f : 0.0f;
                if (V1.y  >= c) code += 2.0f;
                if (nn2.y >= c) code += 4.0f;
                if (V3.y  >= c) code += 8.0f;
                if (ww2.y >= c) code += 16.0f;
                if (V5.y  >= c) code += 32.0f;
                if (ss2.y >= c) code += 64.0f;
                if (V7.y  >= c) code += 128.0f;
                if (gsel) res.w = code; else res.y = code;
            }
        }

        __stcs(reinterpret_cast<float4*>(wp), res);
        wp += W;

        // Commit staged row r+2 into the retiring slot, then prefetch r+3.
        if (r < 7)
            to_row(rows[r % 3], stg);
        if (r < 6)
            load_stage(stg, r + 3);
    }
}

extern "C" void kernel_launch(void* const* d_in, const int* in_sizes, int n_in,
                              void* d_out, int out_size)
{
    const float* x = (const float*)d_in[0];
    float* out = (float*)d_out;

    constexpr int H = 224, W = 224;
    const int planes = out_size / (H * W);   // B*C = 1024

    dim3 block(56, 4, 1);                    // 224 threads
    dim3 grid(1, 7, planes);
    lbp_kernel<<<grid, block>>>(x, out);
}

// round 10
// speedup vs baseline: 1.0749x; 1.0749x over previous
#include <cuda_runtime.h>

// LBP (radius=1, 8 points, skimage 'default') over NCHW fp32, zero boundary.
// Scalar core (bit-stable expressions), 4x8 strip/thread, block (56,4),
// grid (1,7,planes), 4-row rolling buffer with prefetch distance 2.
// New vs round 8:
//  - __launch_bounds__(224, 6): cap regs at 48 -> 6 blocks/SM (42 warps).
//  - interior y-blocks (by=1..5, 5/7 of grid) take a guard-free path: all
//    10 row loads provably in-bounds, zero per-row bounds ISETPs.

template <bool GUARD>
__device__ __forceinline__ void lbp_strip(
    const float* __restrict__ ip, float* __restrict__ op,
    int x0, int y0, bool has_left, bool has_right)
{
    constexpr int H = 224, W = 224;

    // Bilinear weights (float32 of double products, as jax produces).
    const double Fd = 0.70710678;
    const double Gd = 1.0 - Fd;
    const float WD = (float)(Fd * Fd);
    const float WE = (float)(Fd * Gd);
    const float WC = (float)(Gd * Gd);

    // buf[(k+1)&3] holds relative row k, [left, v0..v3, right].
    float buf[4][6];

    const float* base = ip + y0 * W + x0;

    auto load_row = [&](float* b, int k) {
        if (!GUARD || (unsigned)(y0 + k) < (unsigned)H) {
            const float* rp = base + k * W;
            const float4 v = *reinterpret_cast<const float4*>(rp);
            b[0] = has_left  ? __ldg(rp - 1) : 0.0f;
            b[1] = v.x; b[2] = v.y; b[3] = v.z; b[4] = v.w;
            b[5] = has_right ? __ldg(rp + 4) : 0.0f;
        } else {
            b[0] = b[1] = b[2] = b[3] = b[4] = b[5] = 0.0f;
        }
    };

    // Prologue: rows -1, 0, 1; prefetch slot gets row 2 in first iteration.
    load_row(buf[0], -1);
    load_row(buf[1], 0);
    load_row(buf[2], 1);

    float* wp = op + y0 * W + x0;

    #pragma unroll
    for (int r = 0; r < 8; r++) {
        // Prefetch row r+2 (first consumed by compute r+1).
        if (r < 7)
            load_row(buf[(r + 3) & 3], r + 2);

        const float* N = buf[r & 3];
        const float* C = buf[(r + 1) & 3];
        const float* S = buf[(r + 2) & 3];

        float4 res;
        float* resp = &res.x;

        #pragma unroll
        for (int i = 0; i < 4; i++) {
            const float nw = N[i], nn = N[i + 1], ne = N[i + 2];
            const float ww = C[i], c  = C[i + 1], ee = C[i + 2];
            const float sw = S[i], ss = S[i + 1], se = S[i + 2];

            // Diagonal bilinear samples; expressions identical to the
            // bit-stable round-2/8 kernels (same FMA contraction).
            const float v1 = ((WE * nn + WD * ne) + WC * c) + WE * ee; // up-right
            const float v3 = ((WD * nw + WE * nn) + WE * ww) + WC * c; // up-left
            const float v5 = ((WE * ww + WC * c) + WD * sw) + WE * ss; // down-left
            const float v7 = ((WC * c + WE * ee) + WE * ss) + WD * se; // down-right

            float code = (ee >= c) ? 1.0f : 0.0f;   // p=0: east
            if (v1 >= c) code += 2.0f;              // p=1
            if (nn >= c) code += 4.0f;              // p=2: north
            if (v3 >= c) code += 8.0f;              // p=3
            if (ww >= c) code += 16.0f;             // p=4: west
            if (v5 >= c) code += 32.0f;             // p=5
            if (ss >= c) code += 64.0f;             // p=6: south
            if (v7 >= c) code += 128.0f;            // p=7
            resp[i] = code;
        }

        __stcs(reinterpret_cast<float4*>(wp), res);  // streaming store
        wp += W;
    }
}

__global__ __launch_bounds__(224, 6) void lbp_kernel(
    const float* __restrict__ in, float* __restrict__ out)
{
    constexpr int H = 224, W = 224;

    const int plane = blockIdx.z;
    const float* ip = in + (size_t)plane * (H * W);
    float*       op = out + (size_t)plane * (H * W);

    const int tx = threadIdx.x;                        // column group 0..55
    const int x0 = tx * 4;
    const int by = blockIdx.y;
    const int y0 = by * 32 + threadIdx.y * 8;          // strip row base

    const bool has_left  = (tx > 0);
    const bool has_right = (tx < 55);

    if (by >= 1 && by <= 5) {
        // Interior: rows y0-1 .. y0+8 all within [0, 223] -> no bounds checks.
        lbp_strip<false>(ip, op, x0, y0, has_left, has_right);
    } else {
        lbp_strip<true>(ip, op, x0, y0, has_left, has_right);
    }
}

extern "C" void kernel_launch(void* const* d_in, const int* in_sizes, int n_in,
                              void* d_out, int out_size)
{
    const float* x = (const float*)d_in[0];
    float* out = (float*)d_out;

    constexpr int H = 224, W = 224;
    const int planes = out_size / (H * W);   // B*C = 1024

    dim3 block(56, 4, 1);                    // 224 threads = 7 warps
    dim3 grid(1, 7, planes);
    lbp_kernel<<<grid, block>>>(x, out);
}